// round 12
// baseline (speedup 1.0000x reference)
#include <cuda_runtime.h>
#include <cuda_fp16.h>
#include <cstdint>

#define NN 100000
#define NE 1600000
#define F0 256
#define F1 128
#define F2 64
#define EPSV 1e-5f
#define CSRB 64   // blocks running the CSR chain inside the fused kernel

// ---------------- scratch (device globals; no allocations allowed) ----------------
__device__ __align__(16) __half2 g_h1s [NN * F1 / 2];  // fp16 messages: x@W1 (no dinv)
__device__ __align__(16) __half2 g_h2s [NN * F2 / 2];  // fp16 messages: (hbn1@W2)*dinv
__device__ float g_dinv[NN];
__device__ int   g_cnt [NN];     // zero at load; re-zeroed inside fused scan
__device__ int   g_ptr [NN + 1];
__device__ int   g_cursor[NN];
__device__ int   g_srcs[NE];
__device__ int   g_bsum[CSRB];
__device__ unsigned g_barrier[4];  // zero at load; reset by k_agg2_final each launch

// ---------------- helpers ----------------
__device__ __forceinline__ uint32_t smem_u32(const void* p) {
    uint32_t a;
    asm("{ .reg .u64 t; cvta.to.shared.u64 t, %1; cvt.u32.u64 %0, t; }" : "=r"(a) : "l"(p));
    return a;
}
__device__ __forceinline__ void cp16(uint32_t dst, const void* src, bool pred) {
    int sz = pred ? 16 : 0;
    asm volatile("cp.async.cg.shared.global [%0], [%1], 16, %2;"
                 :: "r"(dst), "l"(src), "r"(sz));
}
#define CP_COMMIT() asm volatile("cp.async.commit_group;")
#define CP_WAIT0()  asm volatile("cp.async.wait_group 0;")

__device__ __forceinline__ void split_h2(float x, float y, uint32_t& hi, uint32_t& lo) {
    __half hx = __float2half_rn(x), hy = __float2half_rn(y);
    __half lx = __float2half_rn(x - __half2float(hx));
    __half ly = __float2half_rn(y - __half2float(hy));
    __half2 h = __halves2half2(hx, hy), l = __halves2half2(lx, ly);
    hi = *reinterpret_cast<uint32_t*>(&h);
    lo = *reinterpret_cast<uint32_t*>(&l);
}
__device__ __forceinline__ void mma16816(float* c, const uint32_t* a, const uint32_t* b) {
    asm volatile(
        "mma.sync.aligned.m16n8k16.row.col.f32.f16.f16.f32 "
        "{%0,%1,%2,%3}, {%4,%5,%6,%7}, {%8,%9}, {%0,%1,%2,%3};"
        : "+f"(c[0]), "+f"(c[1]), "+f"(c[2]), "+f"(c[3])
        : "r"(a[0]), "r"(a[1]), "r"(a[2]), "r"(a[3]), "r"(b[0]), "r"(b[1]));
}

// bounded inter-block barrier among the CSRB CSR blocks (never hangs)
__device__ __forceinline__ void csr_barrier(int id) {
    __syncthreads();
    if (threadIdx.x == 0) {
        __threadfence();
        atomicAdd(&g_barrier[id], 1u);
        int it = 0;
        while (atomicAdd(&g_barrier[id], 0u) < (unsigned)CSRB && ++it < (1 << 18)) {}
        __threadfence();
    }
    __syncthreads();
}

// ================= fused kernel: CSR chain (blocks 0..63)  ||  gemm1 (rest) =====
__global__ void __launch_bounds__(256)
k_fused1(const float* __restrict__ x, const float* __restrict__ W1,
         const int* __restrict__ row, const int* __restrict__ col) {
    __shared__ float As[2][128 * 20];
    __shared__ float Bs[2][16 * 132];
    __shared__ int   s_scan[256];

    const int tid = threadIdx.x;

    if (blockIdx.x < CSRB) {
        // ======================= CSR chain =======================
        const int b = blockIdx.x;
        // --- hist ---
        for (int i = b * 256 + tid; i < NE / 2; i += CSRB * 256) {
            int2 c = reinterpret_cast<const int2*>(col)[i];
            atomicAdd(&g_cnt[c.x], 1);
            atomicAdd(&g_cnt[c.y], 1);
        }
        csr_barrier(0);
        // --- scan: 7 elems per thread, block scan, cross-block scan ---
        const int T = 7;                     // 64*256*7 = 114688 >= NN
        int start = (b * 256 + tid) * T;
        int cv[T];
        int lsum = 0;
#pragma unroll
        for (int j = 0; j < T; j++) {
            int idx = start + j;
            int c = (idx < NN) ? g_cnt[idx] : 0;
            cv[j] = c;
            lsum += c;
        }
        s_scan[tid] = lsum;
        __syncthreads();
        for (int off = 1; off < 256; off <<= 1) {
            int v = (tid >= off) ? s_scan[tid - off] : 0;
            __syncthreads();
            s_scan[tid] += v;
            __syncthreads();
        }
        int excl = s_scan[tid] - lsum;
        if (tid == 255) g_bsum[b] = s_scan[255];
        csr_barrier(1);
        if (b == 0) {
            int v = (tid < CSRB) ? g_bsum[tid] : 0;
            s_scan[tid] = v;
            __syncthreads();
            for (int off = 1; off < 256; off <<= 1) {
                int u = (tid >= off) ? s_scan[tid - off] : 0;
                __syncthreads();
                s_scan[tid] += u;
                __syncthreads();
            }
            if (tid < CSRB) g_bsum[tid] = s_scan[tid] - v;  // exclusive
        }
        csr_barrier(2);
        int run = g_bsum[b] + excl;
#pragma unroll
        for (int j = 0; j < T; j++) {
            int idx = start + j;
            if (idx < NN) {
                g_ptr[idx] = run;
                g_cursor[idx] = run;
                g_dinv[idx] = rsqrtf((float)(cv[j] + 1));
                g_cnt[idx] = 0;             // maintain zero invariant
                run += cv[j];
            }
        }
        if (b == 0 && tid == 0) g_ptr[NN] = NE;
        csr_barrier(3);
        // --- scatter ---
        for (int i = b * 256 + tid; i < NE / 2; i += CSRB * 256) {
            int2 r = reinterpret_cast<const int2*>(row)[i];
            int2 c = reinterpret_cast<const int2*>(col)[i];
            g_srcs[atomicAdd(&g_cursor[c.x], 1)] = r.x;
            g_srcs[atomicAdd(&g_cursor[c.y], 1)] = r.y;
        }
    } else {
        // ================== gemm1: h1 = x @ W1 (fp16 out, NO dinv) ==================
        constexpr int NT = F1, KK = F0, BK = 16;
        constexpr int SA = 20, SB = NT + 4;     // 132
        constexpr int WN = NT / 2;              // 64
        constexpr int MSUB = 2, NSUB = WN / 8;  // 8
        constexpr int NSTAGE = KK / BK;         // 16

        const int wid = tid >> 5, lane = tid & 31;
        const int g = lane >> 2, t = lane & 3;
        const int warp_m = wid & 3, warp_n = wid >> 2;
        const int rowBase = (blockIdx.x - CSRB) * 128;

        const uint32_t sAs[2] = { smem_u32(As[0]), smem_u32(As[1]) };
        const uint32_t sBs[2] = { smem_u32(Bs[0]), smem_u32(Bs[1]) };

        float acc[MSUB][NSUB][4];
#pragma unroll
        for (int i = 0; i < MSUB; i++)
#pragma unroll
            for (int j = 0; j < NSUB; j++)
#pragma unroll
                for (int q = 0; q < 4; q++) acc[i][j][q] = 0.f;

        auto load_stage = [&](int s, int buf) {
            int kt = s * BK;
#pragma unroll
            for (int it = 0; it < 2; it++) {
                int idx = tid + it * 256;
                int r = idx >> 2, v = idx & 3;
                int gr = rowBase + r;
                bool ok = gr < NN;
                int gs = ok ? gr : 0;
                cp16(sAs[buf] + (r * SA + v * 4) * 4, &x[(size_t)gs * KK + kt + v * 4], ok);
            }
#pragma unroll
            for (int i = tid; i < BK * NT / 4; i += 256) {
                int r = i / (NT / 4), v = i % (NT / 4);
                cp16(sBs[buf] + (r * SB + v * 4) * 4, &W1[(size_t)(kt + r) * NT + v * 4], true);
            }
            CP_COMMIT();
        };

        load_stage(0, 0);
        for (int s = 0; s < NSTAGE; s++) {
            int b = s & 1;
            CP_WAIT0();
            __syncthreads();
            if (s + 1 < NSTAGE) load_stage(s + 1, b ^ 1);

            const float* as = As[b];
            const float* bs = Bs[b];
            uint32_t bh[NSUB][2], bl[NSUB][2];
#pragma unroll
            for (int sn = 0; sn < NSUB; sn++) {
                int cc = warp_n * WN + sn * 8 + g;
                split_h2(bs[(2 * t) * SB + cc], bs[(2 * t + 1) * SB + cc], bh[sn][0], bl[sn][0]);
                split_h2(bs[(2 * t + 8) * SB + cc], bs[(2 * t + 9) * SB + cc], bh[sn][1], bl[sn][1]);
            }
#pragma unroll
            for (int sm = 0; sm < MSUB; sm++) {
                int r0 = (warp_m * 32 + sm * 16 + g) * SA;
                int r1 = r0 + 8 * SA;
                uint32_t ah[4], al[4];
                split_h2(as[r0 + 2 * t], as[r0 + 2 * t + 1], ah[0], al[0]);
                split_h2(as[r1 + 2 * t], as[r1 + 2 * t + 1], ah[1], al[1]);
                split_h2(as[r0 + 2 * t + 8], as[r0 + 2 * t + 9], ah[2], al[2]);
                split_h2(as[r1 + 2 * t + 8], as[r1 + 2 * t + 9], ah[3], al[3]);
#pragma unroll
                for (int sn = 0; sn < NSUB; sn++) {
                    mma16816(acc[sm][sn], ah, bh[sn]);
                    mma16816(acc[sm][sn], ah, bl[sn]);
                    mma16816(acc[sm][sn], al, bh[sn]);
                }
            }
            __syncthreads();
        }
        // epilogue: plain fp16 store (dinv applied later in agg1 phase)
#pragma unroll
        for (int sm = 0; sm < MSUB; sm++) {
            int gr0 = rowBase + warp_m * 32 + sm * 16 + g;
            int gr1 = gr0 + 8;
#pragma unroll
            for (int sn = 0; sn < NSUB; sn++) {
                int cc = warp_n * WN + sn * 8 + t * 2;
                if (gr0 < NN)
                    g_h1s[((size_t)gr0 * NT + cc) >> 1] =
                        __floats2half2_rn(acc[sm][sn][0], acc[sm][sn][1]);
                if (gr1 < NN)
                    g_h1s[((size_t)gr1 * NT + cc) >> 1] =
                        __floats2half2_rn(acc[sm][sn][2], acc[sm][sn][3]);
            }
        }
    }
}

// ---------------- bn helpers ----------------
__device__ __forceinline__ float bnrelu(float x, float b, float m, float v, float g, float be) {
    float t = (x + b - m) * rsqrtf(v + EPSV) * g + be;
    return t > 0.f ? t : 0.f;
}
__device__ __forceinline__ float4 h2x2_to_f4(uint2 u) {
    float2 p0 = __half22float2(*reinterpret_cast<__half2*>(&u.x));
    float2 p1 = __half22float2(*reinterpret_cast<__half2*>(&u.y));
    return make_float4(p0.x, p0.y, p1.x, p1.y);
}

// ========== fused agg1 + gemm2: block = 128 nodes, hbn1 tile lives in SMEM ======
// Phase 1: 8 warps x 16 nodes gather+BN+ReLU -> sH (fp16, row stride 68 u32)
// Phase 2: h2s[tile] = (sH @ W2) * dinv, fp16 out. A exact fp16 -> 2 MMA terms.
__global__ void __launch_bounds__(256)
k_agg1_gemm2(const float* __restrict__ pb, const float* __restrict__ pm,
             const float* __restrict__ pv, const float* __restrict__ pg,
             const float* __restrict__ pbe, const float* __restrict__ Bmat) {
    constexpr int NT = F2, KK = F1, BK = 16;
    constexpr int SH = 68;                  // u32 (half2) per hbn1 row, padded
    constexpr int SB = NT + 4;              // 68
    constexpr int WN = NT / 2;              // 32
    constexpr int MSUB = 2, NSUB = WN / 8;  // 4
    constexpr int NSTAGE = KK / BK;         // 8

    __shared__ uint32_t sH[128 * SH];       // 34816 B
    __shared__ float    Bs[2][BK * SB];     // 8704 B

    const int tid = threadIdx.x, wid = tid >> 5, lane = tid & 31;
    const int rowBase = blockIdx.x * 128;

    // ---------- phase 1: aggregate 16 nodes per warp ----------
    {
        const uint2* __restrict__ h = reinterpret_cast<const uint2*>(g_h1s);
        for (int j = 0; j < 16; j++) {
            int lr = wid * 16 + j;
            int node = rowBase + lr;
            uint2 st = make_uint2(0u, 0u);
            if (node < NN) {
                float dvv = g_dinv[node];
                int s = g_ptr[node], e = g_ptr[node + 1];
                float4 acc = h2x2_to_f4(__ldg(&h[(size_t)node * 32 + lane]));
                acc.x *= dvv; acc.y *= dvv; acc.z *= dvv; acc.w *= dvv;  // self-loop
                int i = s;
                for (; i + 3 < e; i += 4) {
                    int r0 = g_srcs[i], r1 = g_srcs[i + 1];
                    int r2 = g_srcs[i + 2], r3 = g_srcs[i + 3];
                    float d0 = __ldg(&g_dinv[r0]), d1 = __ldg(&g_dinv[r1]);
                    float d2 = __ldg(&g_dinv[r2]), d3 = __ldg(&g_dinv[r3]);
                    float4 a = h2x2_to_f4(__ldg(&h[(size_t)r0 * 32 + lane]));
                    float4 b = h2x2_to_f4(__ldg(&h[(size_t)r1 * 32 + lane]));
                    float4 c = h2x2_to_f4(__ldg(&h[(size_t)r2 * 32 + lane]));
                    float4 d = h2x2_to_f4(__ldg(&h[(size_t)r3 * 32 + lane]));
                    acc.x += a.x * d0 + b.x * d1 + c.x * d2 + d.x * d3;
                    acc.y += a.y * d0 + b.y * d1 + c.y * d2 + d.y * d3;
                    acc.z += a.z * d0 + b.z * d1 + c.z * d2 + d.z * d3;
                    acc.w += a.w * d0 + b.w * d1 + c.w * d2 + d.w * d3;
                }
                for (; i < e; i++) {
                    int r = g_srcs[i];
                    float dr = __ldg(&g_dinv[r]);
                    float4 a = h2x2_to_f4(__ldg(&h[(size_t)r * 32 + lane]));
                    acc.x += a.x * dr; acc.y += a.y * dr;
                    acc.z += a.z * dr; acc.w += a.w * dr;
                }
                acc.x *= dvv; acc.y *= dvv; acc.z *= dvv; acc.w *= dvv;
                float4 B = reinterpret_cast<const float4*>(pb)[lane];
                float4 M = reinterpret_cast<const float4*>(pm)[lane];
                float4 V = reinterpret_cast<const float4*>(pv)[lane];
                float4 G = reinterpret_cast<const float4*>(pg)[lane];
                float4 E = reinterpret_cast<const float4*>(pbe)[lane];
                float4 o;
                o.x = bnrelu(acc.x, B.x, M.x, V.x, G.x, E.x);
                o.y = bnrelu(acc.y, B.y, M.y, V.y, G.y, E.y);
                o.z = bnrelu(acc.z, B.z, M.z, V.z, G.z, E.z);
                o.w = bnrelu(acc.w, B.w, M.w, V.w, G.w, E.w);
                __half2 p0 = __floats2half2_rn(o.x, o.y);
                __half2 p1 = __floats2half2_rn(o.z, o.w);
                st.x = *reinterpret_cast<uint32_t*>(&p0);
                st.y = *reinterpret_cast<uint32_t*>(&p1);
            }
            // lane l holds feats 4l..4l+3 = u32 idx 2l,2l+1 -> uint2 idx l (stride 34)
            reinterpret_cast<uint2*>(sH)[lr * (SH / 2) + lane] = st;
        }
    }
    __syncthreads();

    // ---------- phase 2: gemm2 from smem A ----------
    const int g = lane >> 2, t = lane & 3;
    const int warp_m = wid & 3, warp_n = wid >> 2;
    const uint32_t sBs[2] = { smem_u32(Bs[0]), smem_u32(Bs[1]) };

    float acc[MSUB][NSUB][4];
#pragma unroll
    for (int i = 0; i < MSUB; i++)
#pragma unroll
        for (int j = 0; j < NSUB; j++)
#pragma unroll
            for (int q = 0; q < 4; q++) acc[i][j][q] = 0.f;

    auto load_B = [&](int s, int buf) {
        int kt = s * BK;
        int r = tid / (NT / 4), v = tid % (NT / 4);    // 256 float4 == 256 threads
        cp16(sBs[buf] + (r * SB + v * 4) * 4, &Bmat[(size_t)(kt + r) * NT + v * 4], true);
        CP_COMMIT();
    };

    load_B(0, 0);
    for (int s = 0; s < NSTAGE; s++) {
        int b = s & 1;
        CP_WAIT0();
        __syncthreads();
        if (s + 1 < NSTAGE) load_B(s + 1, b ^ 1);

        const float* bs = Bs[b];
        uint32_t bh[NSUB][2], bl[NSUB][2];
#pragma unroll
        for (int sn = 0; sn < NSUB; sn++) {
            int cc = warp_n * WN + sn * 8 + g;
            split_h2(bs[(2 * t) * SB + cc], bs[(2 * t + 1) * SB + cc], bh[sn][0], bl[sn][0]);
            split_h2(bs[(2 * t + 8) * SB + cc], bs[(2 * t + 9) * SB + cc], bh[sn][1], bl[sn][1]);
        }
        const int k2 = s * 8;   // u32 (half2) offset within row
#pragma unroll
        for (int sm = 0; sm < MSUB; sm++) {
            int rg = warp_m * 32 + sm * 16 + g;
            uint32_t ah[4];
            ah[0] = sH[rg * SH + k2 + t];
            ah[1] = sH[(rg + 8) * SH + k2 + t];
            ah[2] = sH[rg * SH + k2 + t + 4];
            ah[3] = sH[(rg + 8) * SH + k2 + t + 4];
#pragma unroll
            for (int sn = 0; sn < NSUB; sn++) {
                mma16816(acc[sm][sn], ah, bh[sn]);
                mma16816(acc[sm][sn], ah, bl[sn]);
            }
        }
        __syncthreads();
    }
    // epilogue: dinv scale, fp16 store
#pragma unroll
    for (int sm = 0; sm < MSUB; sm++) {
        int gr0 = rowBase + warp_m * 32 + sm * 16 + g;
        int gr1 = gr0 + 8;
        float dv0 = (gr0 < NN) ? g_dinv[gr0] : 0.f;
        float dv1 = (gr1 < NN) ? g_dinv[gr1] : 0.f;
#pragma unroll
        for (int sn = 0; sn < NSUB; sn++) {
            int cc = warp_n * WN + sn * 8 + t * 2;
            if (gr0 < NN)
                g_h2s[((size_t)gr0 * NT + cc) >> 1] =
                    __floats2half2_rn(acc[sm][sn][0] * dv0, acc[sm][sn][1] * dv0);
            if (gr1 < NN)
                g_h2s[((size_t)gr1 * NT + cc) >> 1] =
                    __floats2half2_rn(acc[sm][sn][2] * dv1, acc[sm][sn][3] * dv1);
        }
    }
}

// layer 2 agg + fused final 64->2 linear; also resets CSR barriers for next launch
__global__ void k_agg2_final(const float* __restrict__ pb, const float* __restrict__ pm,
                             const float* __restrict__ pv, const float* __restrict__ pg,
                             const float* __restrict__ pbe,
                             const float* __restrict__ fcW, const float* __restrict__ fcb,
                             float* __restrict__ out) {
    if (blockIdx.x == 0 && threadIdx.x < 4) g_barrier[threadIdx.x] = 0;
    int gw = (blockIdx.x * blockDim.x + threadIdx.x) >> 5;
    int lane = threadIdx.x & 31;
    if (gw >= NN) return;
    const __half2* __restrict__ h = g_h2s;
    int s = g_ptr[gw], e = g_ptr[gw + 1];
    float2 acc = __half22float2(__ldg(&h[(size_t)gw * 32 + lane]));  // self-loop (dinv folded)
    int i = s;
    for (; i + 3 < e; i += 4) {
        int r0 = g_srcs[i], r1 = g_srcs[i + 1], r2 = g_srcs[i + 2], r3 = g_srcs[i + 3];
        float2 a = __half22float2(__ldg(&h[(size_t)r0 * 32 + lane]));
        float2 b = __half22float2(__ldg(&h[(size_t)r1 * 32 + lane]));
        float2 c = __half22float2(__ldg(&h[(size_t)r2 * 32 + lane]));
        float2 d = __half22float2(__ldg(&h[(size_t)r3 * 32 + lane]));
        acc.x += a.x + b.x + c.x + d.x;
        acc.y += a.y + b.y + c.y + d.y;
    }
    for (; i < e; i++) {
        float2 a = __half22float2(__ldg(&h[(size_t)g_srcs[i] * 32 + lane]));
        acc.x += a.x; acc.y += a.y;
    }
    float dv = g_dinv[gw];
    acc.x *= dv; acc.y *= dv;
    float2 B = reinterpret_cast<const float2*>(pb)[lane];
    float2 M = reinterpret_cast<const float2*>(pm)[lane];
    float2 V = reinterpret_cast<const float2*>(pv)[lane];
    float2 G = reinterpret_cast<const float2*>(pg)[lane];
    float2 E = reinterpret_cast<const float2*>(pbe)[lane];
    float2 o;
    o.x = bnrelu(acc.x, B.x, M.x, V.x, G.x, E.x);
    o.y = bnrelu(acc.y, B.y, M.y, V.y, G.y, E.y);
    float4 w = reinterpret_cast<const float4*>(fcW)[lane];
    float a0 = o.x * w.x + o.y * w.z;
    float a1 = o.x * w.y + o.y * w.w;
#pragma unroll
    for (int off = 16; off; off >>= 1) {
        a0 += __shfl_down_sync(0xffffffffu, a0, off);
        a1 += __shfl_down_sync(0xffffffffu, a1, off);
    }
    if (lane == 0) {
        out[(size_t)gw * 2 + 0] = a0 + fcb[0];
        out[(size_t)gw * 2 + 1] = a1 + fcb[1];
    }
}

// ---------------- launch ----------------
extern "C" void kernel_launch(void* const* d_in, const int* in_sizes, int n_in,
                              void* d_out, int out_size) {
    const float* x   = (const float*)d_in[0];
    const int*   ei  = (const int*)d_in[1];
    const int*   row = ei;
    const int*   col = ei + NE;
    const float* W1  = (const float*)d_in[2];
    const float* b1  = (const float*)d_in[3];
    const float* g1  = (const float*)d_in[4];
    const float* be1 = (const float*)d_in[5];
    const float* m1  = (const float*)d_in[6];
    const float* v1  = (const float*)d_in[7];
    const float* W2  = (const float*)d_in[8];
    const float* b2  = (const float*)d_in[9];
    const float* g2  = (const float*)d_in[10];
    const float* be2 = (const float*)d_in[11];
    const float* m2  = (const float*)d_in[12];
    const float* v2  = (const float*)d_in[13];
    const float* fcW = (const float*)d_in[14];
    const float* fcb = (const float*)d_in[15];
    float* out = (float*)d_out;

    const int NTILES = (NN + 127) / 128;     // 782

    // fused: CSR chain (64 blocks) overlapped with gemm1 (782 blocks)
    k_fused1<<<CSRB + NTILES, 256>>>(x, W1, row, col);
    // fused: agg1 (smem hbn1 tile) + gemm2
    k_agg1_gemm2<<<NTILES, 256>>>(b1, m1, v1, g1, be1, W2);
    // agg2 + final linear (+ barrier reset for next launch)
    k_agg2_final<<<(NN * 32 + 255) / 256, 256>>>(b2, m2, v2, g2, be2, fcW, fcb, out);
}

// round 14
// speedup vs baseline: 1.1987x; 1.1987x over previous
#include <cuda_runtime.h>
#include <cuda_fp16.h>
#include <cstdint>

#define NN 100000
#define NE 1600000
#define F0 256
#define F1 128
#define F2 64
#define EPSV 1e-5f
#define CSRB 64   // blocks running the CSR chain inside the fused kernel

// ---------------- scratch (device globals; no allocations allowed) ----------------
__device__ __align__(16) __half2 g_h1s [NN * F1 / 2];  // fp16 messages: x@W1 (no dinv)
__device__ __align__(16) __half2 g_hbn1[NN * F1 / 2];  // fp16 BN+ReLU(agg1)
__device__ __align__(16) __half2 g_h2s [NN * F2 / 2];  // fp16 messages: (hbn1@W2)*dinv
__device__ float g_dinv[NN];
__device__ int   g_cnt [NN];     // zero at load; re-zeroed inside fused scan
__device__ int   g_ptr [NN + 1];
__device__ int   g_cursor[NN];
__device__ int   g_srcs[NE];
__device__ int   g_bsum[CSRB];
__device__ unsigned g_barrier[4];  // zero at load; reset by k_agg2_final each launch

// ---------------- helpers ----------------
__device__ __forceinline__ uint32_t smem_u32(const void* p) {
    uint32_t a;
    asm("{ .reg .u64 t; cvta.to.shared.u64 t, %1; cvt.u32.u64 %0, t; }" : "=r"(a) : "l"(p));
    return a;
}
__device__ __forceinline__ void cp16(uint32_t dst, const void* src, bool pred) {
    int sz = pred ? 16 : 0;
    asm volatile("cp.async.cg.shared.global [%0], [%1], 16, %2;"
                 :: "r"(dst), "l"(src), "r"(sz));
}
#define CP_COMMIT() asm volatile("cp.async.commit_group;")
#define CP_WAIT0()  asm volatile("cp.async.wait_group 0;")

__device__ __forceinline__ uint32_t pack_h2(float x, float y) {
    __half2 h = __floats2half2_rn(x, y);
    return *reinterpret_cast<uint32_t*>(&h);
}
__device__ __forceinline__ void split_h2(float x, float y, uint32_t& hi, uint32_t& lo) {
    __half hx = __float2half_rn(x), hy = __float2half_rn(y);
    __half lx = __float2half_rn(x - __half2float(hx));
    __half ly = __float2half_rn(y - __half2float(hy));
    __half2 h = __halves2half2(hx, hy), l = __halves2half2(lx, ly);
    hi = *reinterpret_cast<uint32_t*>(&h);
    lo = *reinterpret_cast<uint32_t*>(&l);
}
__device__ __forceinline__ void mma16816(float* c, const uint32_t* a, const uint32_t* b) {
    asm volatile(
        "mma.sync.aligned.m16n8k16.row.col.f32.f16.f16.f32 "
        "{%0,%1,%2,%3}, {%4,%5,%6,%7}, {%8,%9}, {%0,%1,%2,%3};"
        : "+f"(c[0]), "+f"(c[1]), "+f"(c[2]), "+f"(c[3])
        : "r"(a[0]), "r"(a[1]), "r"(a[2]), "r"(a[3]), "r"(b[0]), "r"(b[1]));
}

// bounded inter-block barrier among the CSRB CSR blocks (never hangs)
__device__ __forceinline__ void csr_barrier(int id) {
    __syncthreads();
    if (threadIdx.x == 0) {
        __threadfence();
        atomicAdd(&g_barrier[id], 1u);
        int it = 0;
        while (atomicAdd(&g_barrier[id], 0u) < (unsigned)CSRB && ++it < (1 << 18)) {}
        __threadfence();
    }
    __syncthreads();
}

// ================= fused kernel: CSR chain (blocks 0..63)  ||  gemm1 (rest) =====
// gemm1: A = fp16(x) exact (1 term), B = W1 hi/lo (2 MMA terms total).
__global__ void __launch_bounds__(256)
k_fused1(const float* __restrict__ x, const float* __restrict__ W1,
         const int* __restrict__ row, const int* __restrict__ col) {
    __shared__ float As[2][128 * 20];
    __shared__ float Bs[2][16 * 132];
    __shared__ int   s_scan[256];

    const int tid = threadIdx.x;

    if (blockIdx.x < CSRB) {
        // ======================= CSR chain =======================
        const int b = blockIdx.x;
        // --- hist ---
        for (int i = b * 256 + tid; i < NE / 2; i += CSRB * 256) {
            int2 c = reinterpret_cast<const int2*>(col)[i];
            atomicAdd(&g_cnt[c.x], 1);
            atomicAdd(&g_cnt[c.y], 1);
        }
        csr_barrier(0);
        // --- scan: 7 elems per thread, block scan, cross-block scan ---
        const int T = 7;                     // 64*256*7 = 114688 >= NN
        int start = (b * 256 + tid) * T;
        int cv[T];
        int lsum = 0;
#pragma unroll
        for (int j = 0; j < T; j++) {
            int idx = start + j;
            int c = (idx < NN) ? g_cnt[idx] : 0;
            cv[j] = c;
            lsum += c;
        }
        s_scan[tid] = lsum;
        __syncthreads();
        for (int off = 1; off < 256; off <<= 1) {
            int v = (tid >= off) ? s_scan[tid - off] : 0;
            __syncthreads();
            s_scan[tid] += v;
            __syncthreads();
        }
        int excl = s_scan[tid] - lsum;
        if (tid == 255) g_bsum[b] = s_scan[255];
        csr_barrier(1);
        if (b == 0) {
            int v = (tid < CSRB) ? g_bsum[tid] : 0;
            s_scan[tid] = v;
            __syncthreads();
            for (int off = 1; off < 256; off <<= 1) {
                int u = (tid >= off) ? s_scan[tid - off] : 0;
                __syncthreads();
                s_scan[tid] += u;
                __syncthreads();
            }
            if (tid < CSRB) g_bsum[tid] = s_scan[tid] - v;  // exclusive
        }
        csr_barrier(2);
        int run = g_bsum[b] + excl;
#pragma unroll
        for (int j = 0; j < T; j++) {
            int idx = start + j;
            if (idx < NN) {
                g_ptr[idx] = run;
                g_cursor[idx] = run;
                g_dinv[idx] = rsqrtf((float)(cv[j] + 1));
                g_cnt[idx] = 0;             // maintain zero invariant
                run += cv[j];
            }
        }
        if (b == 0 && tid == 0) g_ptr[NN] = NE;
        csr_barrier(3);
        // --- scatter ---
        for (int i = b * 256 + tid; i < NE / 2; i += CSRB * 256) {
            int2 r = reinterpret_cast<const int2*>(row)[i];
            int2 c = reinterpret_cast<const int2*>(col)[i];
            g_srcs[atomicAdd(&g_cursor[c.x], 1)] = r.x;
            g_srcs[atomicAdd(&g_cursor[c.y], 1)] = r.y;
        }
    } else {
        // ================== gemm1: h1 = x @ W1 (fp16 out, NO dinv) ==================
        constexpr int NT = F1, KK = F0, BK = 16;
        constexpr int SA = 20, SB = NT + 4;     // 132
        constexpr int WN = NT / 2;              // 64
        constexpr int MSUB = 2, NSUB = WN / 8;  // 8
        constexpr int NSTAGE = KK / BK;         // 16

        const int wid = tid >> 5, lane = tid & 31;
        const int g = lane >> 2, t = lane & 3;
        const int warp_m = wid & 3, warp_n = wid >> 2;
        const int rowBase = (blockIdx.x - CSRB) * 128;

        const uint32_t sAs[2] = { smem_u32(As[0]), smem_u32(As[1]) };
        const uint32_t sBs[2] = { smem_u32(Bs[0]), smem_u32(Bs[1]) };

        float acc[MSUB][NSUB][4];
#pragma unroll
        for (int i = 0; i < MSUB; i++)
#pragma unroll
            for (int j = 0; j < NSUB; j++)
#pragma unroll
                for (int q = 0; q < 4; q++) acc[i][j][q] = 0.f;

        auto load_stage = [&](int s, int buf) {
            int kt = s * BK;
#pragma unroll
            for (int it = 0; it < 2; it++) {
                int idx = tid + it * 256;
                int r = idx >> 2, v = idx & 3;
                int gr = rowBase + r;
                bool ok = gr < NN;
                int gs = ok ? gr : 0;
                cp16(sAs[buf] + (r * SA + v * 4) * 4, &x[(size_t)gs * KK + kt + v * 4], ok);
            }
#pragma unroll
            for (int i = tid; i < BK * NT / 4; i += 256) {
                int r = i / (NT / 4), v = i % (NT / 4);
                cp16(sBs[buf] + (r * SB + v * 4) * 4, &W1[(size_t)(kt + r) * NT + v * 4], true);
            }
            CP_COMMIT();
        };

        load_stage(0, 0);
        for (int s = 0; s < NSTAGE; s++) {
            int b = s & 1;
            CP_WAIT0();
            __syncthreads();
            if (s + 1 < NSTAGE) load_stage(s + 1, b ^ 1);

            const float* as = As[b];
            const float* bs = Bs[b];
            uint32_t bh[NSUB][2], bl[NSUB][2];
#pragma unroll
            for (int sn = 0; sn < NSUB; sn++) {
                int cc = warp_n * WN + sn * 8 + g;
                split_h2(bs[(2 * t) * SB + cc], bs[(2 * t + 1) * SB + cc], bh[sn][0], bl[sn][0]);
                split_h2(bs[(2 * t + 8) * SB + cc], bs[(2 * t + 9) * SB + cc], bh[sn][1], bl[sn][1]);
            }
#pragma unroll
            for (int sm = 0; sm < MSUB; sm++) {
                int r0 = (warp_m * 32 + sm * 16 + g) * SA;
                int r1 = r0 + 8 * SA;
                uint32_t ah[4];
                ah[0] = pack_h2(as[r0 + 2 * t],     as[r0 + 2 * t + 1]);
                ah[1] = pack_h2(as[r1 + 2 * t],     as[r1 + 2 * t + 1]);
                ah[2] = pack_h2(as[r0 + 2 * t + 8], as[r0 + 2 * t + 9]);
                ah[3] = pack_h2(as[r1 + 2 * t + 8], as[r1 + 2 * t + 9]);
#pragma unroll
                for (int sn = 0; sn < NSUB; sn++) {
                    mma16816(acc[sm][sn], ah, bh[sn]);   // A*Bhi
                    mma16816(acc[sm][sn], ah, bl[sn]);   // A*Blo
                }
            }
            __syncthreads();
        }
        // epilogue: plain fp16 store (dinv applied later in agg1)
#pragma unroll
        for (int sm = 0; sm < MSUB; sm++) {
            int gr0 = rowBase + warp_m * 32 + sm * 16 + g;
            int gr1 = gr0 + 8;
#pragma unroll
            for (int sn = 0; sn < NSUB; sn++) {
                int cc = warp_n * WN + sn * 8 + t * 2;
                if (gr0 < NN)
                    g_h1s[((size_t)gr0 * NT + cc) >> 1] =
                        __floats2half2_rn(acc[sm][sn][0], acc[sm][sn][1]);
                if (gr1 < NN)
                    g_h1s[((size_t)gr1 * NT + cc) >> 1] =
                        __floats2half2_rn(acc[sm][sn][2], acc[sm][sn][3]);
            }
        }
    }
}

// ---------------- bn helpers ----------------
__device__ __forceinline__ float bnrelu(float x, float b, float m, float v, float g, float be) {
    float t = (x + b - m) * rsqrtf(v + EPSV) * g + be;
    return t > 0.f ? t : 0.f;
}
__device__ __forceinline__ float4 h2x2_to_f4(uint2 u) {
    float2 p0 = __half22float2(*reinterpret_cast<__half2*>(&u.x));
    float2 p1 = __half22float2(*reinterpret_cast<__half2*>(&u.y));
    return make_float4(p0.x, p0.y, p1.x, p1.y);
}

// layer 1 agg: warp-per-node (independent warps; no block coupling), fp16 out
__global__ void k_agg1(const float* __restrict__ pb, const float* __restrict__ pm,
                       const float* __restrict__ pv, const float* __restrict__ pg,
                       const float* __restrict__ pbe) {
    int gw = (blockIdx.x * blockDim.x + threadIdx.x) >> 5;
    int lane = threadIdx.x & 31;
    if (gw >= NN) return;
    const uint2* __restrict__ h = reinterpret_cast<const uint2*>(g_h1s);
    float dvv = g_dinv[gw];
    int s = g_ptr[gw], e = g_ptr[gw + 1];
    float4 acc = h2x2_to_f4(__ldg(&h[(size_t)gw * 32 + lane]));
    acc.x *= dvv; acc.y *= dvv; acc.z *= dvv; acc.w *= dvv;   // self-loop term
    int i = s;
    for (; i + 3 < e; i += 4) {
        int r0 = g_srcs[i], r1 = g_srcs[i + 1], r2 = g_srcs[i + 2], r3 = g_srcs[i + 3];
        float d0 = __ldg(&g_dinv[r0]), d1 = __ldg(&g_dinv[r1]);
        float d2 = __ldg(&g_dinv[r2]), d3 = __ldg(&g_dinv[r3]);
        float4 a = h2x2_to_f4(__ldg(&h[(size_t)r0 * 32 + lane]));
        float4 b = h2x2_to_f4(__ldg(&h[(size_t)r1 * 32 + lane]));
        float4 c = h2x2_to_f4(__ldg(&h[(size_t)r2 * 32 + lane]));
        float4 d = h2x2_to_f4(__ldg(&h[(size_t)r3 * 32 + lane]));
        acc.x += a.x * d0 + b.x * d1 + c.x * d2 + d.x * d3;
        acc.y += a.y * d0 + b.y * d1 + c.y * d2 + d.y * d3;
        acc.z += a.z * d0 + b.z * d1 + c.z * d2 + d.z * d3;
        acc.w += a.w * d0 + b.w * d1 + c.w * d2 + d.w * d3;
    }
    for (; i < e; i++) {
        int r = g_srcs[i];
        float dr = __ldg(&g_dinv[r]);
        float4 a = h2x2_to_f4(__ldg(&h[(size_t)r * 32 + lane]));
        acc.x += a.x * dr; acc.y += a.y * dr; acc.z += a.z * dr; acc.w += a.w * dr;
    }
    acc.x *= dvv; acc.y *= dvv; acc.z *= dvv; acc.w *= dvv;
    float4 B = reinterpret_cast<const float4*>(pb)[lane];
    float4 M = reinterpret_cast<const float4*>(pm)[lane];
    float4 V = reinterpret_cast<const float4*>(pv)[lane];
    float4 G = reinterpret_cast<const float4*>(pg)[lane];
    float4 E = reinterpret_cast<const float4*>(pbe)[lane];
    float4 o;
    o.x = bnrelu(acc.x, B.x, M.x, V.x, G.x, E.x);
    o.y = bnrelu(acc.y, B.y, M.y, V.y, G.y, E.y);
    o.z = bnrelu(acc.z, B.z, M.z, V.z, G.z, E.z);
    o.w = bnrelu(acc.w, B.w, M.w, V.w, G.w, E.w);
    __half2 p0 = __floats2half2_rn(o.x, o.y);
    __half2 p1 = __floats2half2_rn(o.z, o.w);
    uint2 st;
    st.x = *reinterpret_cast<uint32_t*>(&p0);
    st.y = *reinterpret_cast<uint32_t*>(&p1);
    reinterpret_cast<uint2*>(g_hbn1)[(size_t)gw * 32 + lane] = st;
}

// ================= gemm2: h2s = (hbn1_fp16 @ W2) * dinv, fp16 out ===============
// A exact fp16 -> 2 MMA terms.
__global__ void __launch_bounds__(256)
mma_gemm2(const float* __restrict__ Bmat) {
    constexpr int NT = F2, KK = F1, BK = 16;
    constexpr int SA2 = 12;                 // u32 (half2) per A row, padded
    constexpr int SB = NT + 4;              // 68
    constexpr int WN = NT / 2;              // 32
    constexpr int MSUB = 2, NSUB = WN / 8;  // 4
    constexpr int NSTAGE = KK / BK;         // 8

    __shared__ uint32_t As2[2][128 * SA2];
    __shared__ float    Bs[2][BK * SB];

    const int tid = threadIdx.x, wid = tid >> 5, lane = tid & 31;
    const int g = lane >> 2, t = lane & 3;
    const int warp_m = wid & 3, warp_n = wid >> 2;
    const int rowBase = blockIdx.x * 128;

    const uint32_t sAs[2] = { smem_u32(As2[0]), smem_u32(As2[1]) };
    const uint32_t sBs[2] = { smem_u32(Bs[0]), smem_u32(Bs[1]) };
    const __half2* __restrict__ Ah = g_hbn1;

    float acc[MSUB][NSUB][4];
#pragma unroll
    for (int i = 0; i < MSUB; i++)
#pragma unroll
        for (int j = 0; j < NSUB; j++)
#pragma unroll
            for (int q = 0; q < 4; q++) acc[i][j][q] = 0.f;

    auto load_stage = [&](int s, int buf) {
        int kt = s * BK;
        {
            int r = tid >> 1, v = tid & 1;
            int gr = rowBase + r;
            bool ok = gr < NN;
            int gs = ok ? gr : 0;
            cp16(sAs[buf] + (r * SA2 + v * 4) * 4,
                 &Ah[(size_t)gs * (KK / 2) + kt / 2 + v * 4], ok);
        }
        {
            int r = tid / (NT / 4), v = tid % (NT / 4);
            cp16(sBs[buf] + (r * SB + v * 4) * 4, &Bmat[(size_t)(kt + r) * NT + v * 4], true);
        }
        CP_COMMIT();
    };

    load_stage(0, 0);
    for (int s = 0; s < NSTAGE; s++) {
        int b = s & 1;
        CP_WAIT0();
        __syncthreads();
        if (s + 1 < NSTAGE) load_stage(s + 1, b ^ 1);

        const uint32_t* as = As2[b];
        const float* bs = Bs[b];
        uint32_t bh[NSUB][2], bl[NSUB][2];
#pragma unroll
        for (int sn = 0; sn < NSUB; sn++) {
            int cc = warp_n * WN + sn * 8 + g;
            split_h2(bs[(2 * t) * SB + cc], bs[(2 * t + 1) * SB + cc], bh[sn][0], bl[sn][0]);
            split_h2(bs[(2 * t + 8) * SB + cc], bs[(2 * t + 9) * SB + cc], bh[sn][1], bl[sn][1]);
        }
#pragma unroll
        for (int sm = 0; sm < MSUB; sm++) {
            int rg = warp_m * 32 + sm * 16 + g;
            uint32_t ah[4];
            ah[0] = as[rg * SA2 + t];
            ah[1] = as[(rg + 8) * SA2 + t];
            ah[2] = as[rg * SA2 + t + 4];
            ah[3] = as[(rg + 8) * SA2 + t + 4];
#pragma unroll
            for (int sn = 0; sn < NSUB; sn++) {
                mma16816(acc[sm][sn], ah, bh[sn]);
                mma16816(acc[sm][sn], ah, bl[sn]);
            }
        }
        __syncthreads();
    }
    // epilogue: dinv scale, fp16 store
#pragma unroll
    for (int sm = 0; sm < MSUB; sm++) {
        int gr0 = rowBase + warp_m * 32 + sm * 16 + g;
        int gr1 = gr0 + 8;
        float dv0 = (gr0 < NN) ? g_dinv[gr0] : 0.f;
        float dv1 = (gr1 < NN) ? g_dinv[gr1] : 0.f;
#pragma unroll
        for (int sn = 0; sn < NSUB; sn++) {
            int cc = warp_n * WN + sn * 8 + t * 2;
            if (gr0 < NN)
                g_h2s[((size_t)gr0 * NT + cc) >> 1] =
                    __floats2half2_rn(acc[sm][sn][0] * dv0, acc[sm][sn][1] * dv0);
            if (gr1 < NN)
                g_h2s[((size_t)gr1 * NT + cc) >> 1] =
                    __floats2half2_rn(acc[sm][sn][2] * dv1, acc[sm][sn][3] * dv1);
        }
    }
}

// layer 2 agg + fused final 64->2 linear; also resets CSR barriers for next launch
__global__ void k_agg2_final(const float* __restrict__ pb, const float* __restrict__ pm,
                             const float* __restrict__ pv, const float* __restrict__ pg,
                             const float* __restrict__ pbe,
                             const float* __restrict__ fcW, const float* __restrict__ fcb,
                             float* __restrict__ out) {
    if (blockIdx.x == 0 && threadIdx.x < 4) g_barrier[threadIdx.x] = 0;
    int gw = (blockIdx.x * blockDim.x + threadIdx.x) >> 5;
    int lane = threadIdx.x & 31;
    if (gw >= NN) return;
    const __half2* __restrict__ h = g_h2s;
    int s = g_ptr[gw], e = g_ptr[gw + 1];
    float2 acc = __half22float2(__ldg(&h[(size_t)gw * 32 + lane]));  // self-loop (dinv folded)
    int i = s;
    for (; i + 3 < e; i += 4) {
        int r0 = g_srcs[i], r1 = g_srcs[i + 1], r2 = g_srcs[i + 2], r3 = g_srcs[i + 3];
        float2 a = __half22float2(__ldg(&h[(size_t)r0 * 32 + lane]));
        float2 b = __half22float2(__ldg(&h[(size_t)r1 * 32 + lane]));
        float2 c = __half22float2(__ldg(&h[(size_t)r2 * 32 + lane]));
        float2 d = __half22float2(__ldg(&h[(size_t)r3 * 32 + lane]));
        acc.x += a.x + b.x + c.x + d.x;
        acc.y += a.y + b.y + c.y + d.y;
    }
    for (; i < e; i++) {
        float2 a = __half22float2(__ldg(&h[(size_t)g_srcs[i] * 32 + lane]));
        acc.x += a.x; acc.y += a.y;
    }
    float dv = g_dinv[gw];
    acc.x *= dv; acc.y *= dv;
    float2 B = reinterpret_cast<const float2*>(pb)[lane];
    float2 M = reinterpret_cast<const float2*>(pm)[lane];
    float2 V = reinterpret_cast<const float2*>(pv)[lane];
    float2 G = reinterpret_cast<const float2*>(pg)[lane];
    float2 E = reinterpret_cast<const float2*>(pbe)[lane];
    float2 o;
    o.x = bnrelu(acc.x, B.x, M.x, V.x, G.x, E.x);
    o.y = bnrelu(acc.y, B.y, M.y, V.y, G.y, E.y);
    float4 w = reinterpret_cast<const float4*>(fcW)[lane];
    float a0 = o.x * w.x + o.y * w.z;
    float a1 = o.x * w.y + o.y * w.w;
#pragma unroll
    for (int off = 16; off; off >>= 1) {
        a0 += __shfl_down_sync(0xffffffffu, a0, off);
        a1 += __shfl_down_sync(0xffffffffu, a1, off);
    }
    if (lane == 0) {
        out[(size_t)gw * 2 + 0] = a0 + fcb[0];
        out[(size_t)gw * 2 + 1] = a1 + fcb[1];
    }
}

// ---------------- launch ----------------
extern "C" void kernel_launch(void* const* d_in, const int* in_sizes, int n_in,
                              void* d_out, int out_size) {
    const float* x   = (const float*)d_in[0];
    const int*   ei  = (const int*)d_in[1];
    const int*   row = ei;
    const int*   col = ei + NE;
    const float* W1  = (const float*)d_in[2];
    const float* b1  = (const float*)d_in[3];
    const float* g1  = (const float*)d_in[4];
    const float* be1 = (const float*)d_in[5];
    const float* m1  = (const float*)d_in[6];
    const float* v1  = (const float*)d_in[7];
    const float* W2  = (const float*)d_in[8];
    const float* b2  = (const float*)d_in[9];
    const float* g2  = (const float*)d_in[10];
    const float* be2 = (const float*)d_in[11];
    const float* m2  = (const float*)d_in[12];
    const float* v2  = (const float*)d_in[13];
    const float* fcW = (const float*)d_in[14];
    const float* fcb = (const float*)d_in[15];
    float* out = (float*)d_out;

    const int NTILES = (NN + 127) / 128;     // 782

    // fused: CSR chain (64 blocks) overlapped with gemm1 (782 blocks)
    k_fused1<<<CSRB + NTILES, 256>>>(x, W1, row, col);
    // layer 1 aggregation (independent warps)
    k_agg1<<<(NN * 32 + 255) / 256, 256>>>(b1, m1, v1, g1, be1);
    // layer 2 GEMM
    mma_gemm2<<<NTILES, 256>>>(W2);
    // agg2 + final linear (+ barrier reset for next launch)
    k_agg2_final<<<(NN * 32 + 255) / 256, 256>>>(b2, m2, v2, g2, be2, fcW, fcb, out);
}